// round 12
// baseline (speedup 1.0000x reference)
#include <cuda_runtime.h>
#include <cuda_bf16.h>
#include <math.h>

#define D_MODEL 1024
#define N_HEADS 16
#define D_K     64
#define BATCH   2
#define SEQ     2048
#define M_ROWS  (BATCH * SEQ)          // 4096

// Scratch for Q,K,V in [B,H,S,Dk] layout (no cudaMalloc allowed)
__device__ float g_Q[M_ROWS * D_MODEL];
__device__ float g_K[M_ROWS * D_MODEL];
__device__ float g_V[M_ROWS * D_MODEL];

// ---- packed f32x2 helpers (Blackwell FFMA2 path) --------------------------
// Free pair reinterpretation of a 16B-aligned float4 (no instructions).
union F4U2 {
    float4 f4;
    unsigned long long u2[2];
};

__device__ __forceinline__ unsigned long long dup2(float v) {
    unsigned long long r;
    asm("mov.b64 %0, {%1, %1};" : "=l"(r) : "r"(__float_as_uint(v)));
    return r;
}
__device__ __forceinline__ void upk2(unsigned long long p, float& lo, float& hi) {
    unsigned int a, b;
    asm("mov.b64 {%0, %1}, %2;" : "=r"(a), "=r"(b) : "l"(p));
    lo = __uint_as_float(a);
    hi = __uint_as_float(b);
}
#define FMA2(d, a, b, c) \
    asm("fma.rn.f32x2 %0, %1, %2, %3;" : "=l"(d) : "l"(a), "l"(b), "l"(c))

// Raw 2^x (MUFU.EX2). Q is pre-scaled by 1/sqrt(Dk) * log2(e), so
// ex2f(s) == exp(s_true) with no per-element FMUL.
__device__ __forceinline__ float ex2f(float x) {
    float r;
    asm("ex2.approx.f32 %0, %1;" : "=f"(r) : "f"(x));
    return r;
}

// ---------------------------------------------------------------------------
// Fused QKV SGEMM: gridDim.z selects (Wq,bq,Q*qscale) / (Wk,bk,K) / (Wv,bv,V).
// BM=BN=128, BK=16, 256 threads, 8x8 micro-tile via f32x2 (8 rows x 4 pairs),
// register-prefetch pipelining. B-operand pairs are free reinterprets.
// Inner loop per k: 4 LDS.128 + 8 dup + 32 FFMA2 -> fma-pipe bound (floor).
// ---------------------------------------------------------------------------
#define BM 128
#define BN 128
#define BKK 16

// 1/sqrt(D_K) * log2(e): folds both the attention scale and the exp->ex2
// conversion into the Q projection (bilinear in Q, so exact).
#define QSCALE 0.1803368801111204f

__global__ __launch_bounds__(256)
void qkv_gemm_fused_kernel(const float* __restrict__ X,
                           const float* __restrict__ Wq,
                           const float* __restrict__ bq,
                           const float* __restrict__ Wk,
                           const float* __restrict__ bk,
                           const float* __restrict__ Wv,
                           const float* __restrict__ bv,
                           float* __restrict__ Qo,
                           float* __restrict__ Ko,
                           float* __restrict__ Vo)
{
    __shared__ float As[BKK][132];   // A transposed [k][m]
    __shared__ float Bs[BKK][128];   // B [k][n]

    const int z = blockIdx.z;
    const float* W    = (z == 0) ? Wq : (z == 1) ? Wk : Wv;
    const float* bias = (z == 0) ? bq : (z == 1) ? bk : bv;
    float*       out  = (z == 0) ? Qo : (z == 1) ? Ko : Vo;
    const float out_scale = (z == 0) ? QSCALE : 1.0f;

    const int tid = threadIdx.x;
    const int m0 = blockIdx.y * BM;
    const int n0 = blockIdx.x * BN;
    const int tx = tid & 15;
    const int ty = tid >> 4;

    const int arow = tid >> 1;        // 0..127
    const int ac4  = tid & 1;         // 0..1 (and +2 for second 8 k)
    const int brow = tid >> 5;        // 0..7 (and +8)
    const int bc4  = tid & 31;        // 0..31

    const float4* X4 = (const float4*)X;
    const float4* W4 = (const float4*)W;

    unsigned long long accp[8][4] = {};   // 8 rows x 4 col-pairs (cols 2j,2j+1)

    float4 pa0 = X4[(size_t)(m0 + arow) * (D_MODEL / 4) + ac4];
    float4 pa1 = X4[(size_t)(m0 + arow) * (D_MODEL / 4) + 2 + ac4];
    float4 pb0 = W4[(size_t)brow * (D_MODEL / 4) + (n0 >> 2) + bc4];
    float4 pb1 = W4[(size_t)(brow + 8) * (D_MODEL / 4) + (n0 >> 2) + bc4];

    const int NKB = D_MODEL / BKK;    // 64
    for (int kb = 0; kb < NKB; kb++) {
        As[ac4 * 4 + 0][arow] = pa0.x;
        As[ac4 * 4 + 1][arow] = pa0.y;
        As[ac4 * 4 + 2][arow] = pa0.z;
        As[ac4 * 4 + 3][arow] = pa0.w;
        As[8 + ac4 * 4 + 0][arow] = pa1.x;
        As[8 + ac4 * 4 + 1][arow] = pa1.y;
        As[8 + ac4 * 4 + 2][arow] = pa1.z;
        As[8 + ac4 * 4 + 3][arow] = pa1.w;
        *(float4*)&Bs[brow][bc4 * 4]     = pb0;
        *(float4*)&Bs[brow + 8][bc4 * 4] = pb1;
        __syncthreads();

        if (kb + 1 < NKB) {
            pa0 = X4[(size_t)(m0 + arow) * (D_MODEL / 4) + (kb + 1) * 4 + ac4];
            pa1 = X4[(size_t)(m0 + arow) * (D_MODEL / 4) + (kb + 1) * 4 + 2 + ac4];
            pb0 = W4[(size_t)((kb + 1) * BKK + brow) * (D_MODEL / 4) + (n0 >> 2) + bc4];
            pb1 = W4[(size_t)((kb + 1) * BKK + brow + 8) * (D_MODEL / 4) + (n0 >> 2) + bc4];
        }

        #pragma unroll
        for (int k = 0; k < BKK; k++) {
            float4 a0 = *(const float4*)&As[k][ty * 8];
            float4 a1 = *(const float4*)&As[k][ty * 8 + 4];
            F4U2 b0, b1;
            b0.f4 = *(const float4*)&Bs[k][tx * 8];
            b1.f4 = *(const float4*)&Bs[k][tx * 8 + 4];
            float av[8] = {a0.x, a0.y, a0.z, a0.w, a1.x, a1.y, a1.z, a1.w};
            #pragma unroll
            for (int i = 0; i < 8; i++) {
                unsigned long long aa = dup2(av[i]);
                FMA2(accp[i][0], aa, b0.u2[0], accp[i][0]);
                FMA2(accp[i][1], aa, b0.u2[1], accp[i][1]);
                FMA2(accp[i][2], aa, b1.u2[0], accp[i][2]);
                FMA2(accp[i][3], aa, b1.u2[1], accp[i][3]);
            }
        }
        __syncthreads();
    }

    // Epilogue: unpack pairs, bias + scale, scatter into [B,H,S,Dk].
    // Bias is i-invariant: one float4 per jg, hoisted out of the i-loop.
    float4 bb[2];
    bb[0] = *(const float4*)&bias[n0 + tx * 8];
    bb[1] = *(const float4*)&bias[n0 + tx * 8 + 4];
    #pragma unroll
    for (int i = 0; i < 8; i++) {
        int m = m0 + ty * 8 + i;
        int b = m >> 11;
        int s = m & (SEQ - 1);
        #pragma unroll
        for (int jg = 0; jg < 2; jg++) {
            int n = n0 + tx * 8 + jg * 4;
            int h = n >> 6;
            int d = n & 63;
            float c0, c1, c2, c3;
            upk2(accp[i][2 * jg + 0], c0, c1);
            upk2(accp[i][2 * jg + 1], c2, c3);
            float4 v;
            v.x = (c0 + bb[jg].x) * out_scale;
            v.y = (c1 + bb[jg].y) * out_scale;
            v.z = (c2 + bb[jg].z) * out_scale;
            v.w = (c3 + bb[jg].w) * out_scale;
            *(float4*)&out[(((size_t)b * N_HEADS + h) * SEQ + s) * D_K + d] = v;
        }
    }
}

// ---------------------------------------------------------------------------
// Attention: one CTA per (b,h, 128-query tile). K/V streamed in 64-row chunks
// with register double-buffering. 256 threads, 8x4 micro-tile, FFMA2.
// S-loop: accumulators packed over query-row PAIRS -> Q pairs are free
// reinterprets of d-major LDS.128; only 4 K-scalar dups per d (fma-bound).
// P = ex2(S) directly (log2e folded into Q projection; no per-element FMUL).
// P exchange is WARP-LOCAL -> __syncwarp instead of __syncthreads.
// PV-loop: kk in blocks of 4; P rows loaded as float4, V col-pairs free.
// Row sums: per-lane partials accumulated across ALL chunks; the cross-lane
// shfl_xor butterfly runs ONCE after the mainloop (linearity), cutting SHFL
// count 32x vs per-chunk reduction.
// O_row = (sum_k ex2(s) * V) / (sum_k ex2(s) + 1e-8).
// ---------------------------------------------------------------------------
#define QT 128
#define KT 64
#define QT_PAD 132
#define KV_PAD 68
// smem floats: Qt[64][132] Kt[64][68] Vs[64][68] Ps[128][68]
#define SM_FLOATS (64 * QT_PAD + 64 * KV_PAD + 64 * KV_PAD + QT * KV_PAD)

__global__ __launch_bounds__(256, 2)
void attn_kernel(const float* __restrict__ Q,
                 const float* __restrict__ K,
                 const float* __restrict__ V,
                 float* __restrict__ out)
{
    extern __shared__ float sm[];
    float* Qt   = sm;                        // [64][132]  d-major Q
    float* Kt   = Qt + 64 * QT_PAD;          // [64][68]   d-major K chunk
    float* Vs   = Kt + 64 * KV_PAD;          // [64][68]   row-major V chunk
    float* Ps   = Vs + 64 * KV_PAD;          // [128][68]

    const int qt = blockIdx.x;               // 0..15
    const int bh = blockIdx.y;               // 0..31
    const int b  = bh >> 4;
    const int h  = bh & 15;

    const float* Qb = Q + (size_t)bh * SEQ * D_K;
    const float* Kb = K + (size_t)bh * SEQ * D_K;
    const float* Vb = V + (size_t)bh * SEQ * D_K;

    const int tid = threadIdx.x;
    const int ty  = tid >> 4;                // 0..15 -> 8 query rows
    const int tx  = tid & 15;                // 0..15 -> 4 key cols

    // Load Q tile, transpose to d-major (gmem coalesced float4)
    {
        const float4* Q4 = (const float4*)(Qb + (size_t)qt * QT * D_K);
        for (int i = tid; i < QT * D_K / 4; i += 256) {
            int r  = i >> 4;
            int c4 = i & 15;
            float4 q = Q4[i];
            Qt[(4 * c4 + 0) * QT_PAD + r] = q.x;
            Qt[(4 * c4 + 1) * QT_PAD + r] = q.y;
            Qt[(4 * c4 + 2) * QT_PAD + r] = q.z;
            Qt[(4 * c4 + 3) * QT_PAD + r] = q.w;
        }
    }

    unsigned long long o01[8] = {}, o23[8] = {};   // O accumulator (col pairs)
    float lsum[8] = {};   // per-lane partial row sums (this lane's 4 columns)

    // register prefetch of chunk 0 (4 float4 each of K and V per thread)
    float4 kreg[4], vreg[4];
    {
        const float4* K4 = (const float4*)Kb;
        const float4* V4 = (const float4*)Vb;
        #pragma unroll
        for (int u = 0; u < 4; u++) {
            kreg[u] = K4[tid + 256 * u];
            vreg[u] = V4[tid + 256 * u];
        }
    }

    const int NCHUNK = SEQ / KT;             // 32
    for (int kc = 0; kc < NCHUNK; kc++) {
        // commit prefetched chunk (K transposed d-major, V row-major)
        #pragma unroll
        for (int u = 0; u < 4; u++) {
            int i  = tid + 256 * u;
            int r  = i >> 4;
            int c4 = i & 15;
            Kt[(4 * c4 + 0) * KV_PAD + r] = kreg[u].x;
            Kt[(4 * c4 + 1) * KV_PAD + r] = kreg[u].y;
            Kt[(4 * c4 + 2) * KV_PAD + r] = kreg[u].z;
            Kt[(4 * c4 + 3) * KV_PAD + r] = kreg[u].w;
            *(float4*)&Vs[r * KV_PAD + 4 * c4] = vreg[u];
        }
        __syncthreads();

        // prefetch next chunk while computing this one
        if (kc + 1 < NCHUNK) {
            const float4* K4 = (const float4*)(Kb + (size_t)(kc + 1) * KT * D_K);
            const float4* V4 = (const float4*)(Vb + (size_t)(kc + 1) * KT * D_K);
            #pragma unroll
            for (int u = 0; u < 4; u++) {
                kreg[u] = K4[tid + 256 * u];
                vreg[u] = V4[tid + 256 * u];
            }
        }

        // S = Q @ K^T. sp[p][j]: lanes = rows (2p, 2p+1), col tx*4+j.
        // Per d: 3 LDS.128 + 4 dups + 16 FFMA2 -> fma-pipe bound.
        unsigned long long sp[4][4] = {};
        #pragma unroll 8
        for (int d = 0; d < D_K; d++) {
            F4U2 kv, a0, a1;
            kv.f4 = *(const float4*)&Kt[d * KV_PAD + tx * 4];
            a0.f4 = *(const float4*)&Qt[d * QT_PAD + ty * 8];
            a1.f4 = *(const float4*)&Qt[d * QT_PAD + ty * 8 + 4];
            unsigned long long kd0 = dup2(kv.f4.x);
            unsigned long long kd1 = dup2(kv.f4.y);
            unsigned long long kd2 = dup2(kv.f4.z);
            unsigned long long kd3 = dup2(kv.f4.w);
            unsigned long long qp[4] = {a0.u2[0], a0.u2[1], a1.u2[0], a1.u2[1]};
            #pragma unroll
            for (int p = 0; p < 4; p++) {
                FMA2(sp[p][0], qp[p], kd0, sp[p][0]);
                FMA2(sp[p][1], qp[p], kd1, sp[p][1]);
                FMA2(sp[p][2], qp[p], kd2, sp[p][2]);
                FMA2(sp[p][3], qp[p], kd3, sp[p][3]);
            }
        }

        // P = ex2(S) -> shared; accumulate per-lane partial row sums only
        // (cross-lane butterfly deferred to after the mainloop).
        #pragma unroll
        for (int p = 0; p < 4; p++) {
            float s0j[4], s1j[4];
            #pragma unroll
            for (int j = 0; j < 4; j++) upk2(sp[p][j], s0j[j], s1j[j]);
            int r0 = ty * 8 + 2 * p;
            float4 p0, p1;
            p0.x = ex2f(s0j[0]); p0.y = ex2f(s0j[1]);
            p0.z = ex2f(s0j[2]); p0.w = ex2f(s0j[3]);
            p1.x = ex2f(s1j[0]); p1.y = ex2f(s1j[1]);
            p1.z = ex2f(s1j[2]); p1.w = ex2f(s1j[3]);
            *(float4*)&Ps[r0 * KV_PAD + tx * 4]       = p0;
            *(float4*)&Ps[(r0 + 1) * KV_PAD + tx * 4] = p1;
            lsum[2 * p]     += (p0.x + p0.y) + (p0.z + p0.w);
            lsum[2 * p + 1] += (p1.x + p1.y) + (p1.z + p1.w);
        }
        // P producer/consumer pairs are warp-local: row r is written and read
        // only by ty-group r/8, and a warp = two aligned ty-groups.
        __syncwarp();

        // O += P @ V : kk in blocks of 4; P rows as float4 (broadcast reads),
        // V col-pairs free. Per 4 kk: 12 LDS.128 + 32 dup + 64 FFMA2.
        #pragma unroll 2
        for (int kk4 = 0; kk4 < KT / 4; kk4++) {
            F4U2 vv[4];
            #pragma unroll
            for (int j = 0; j < 4; j++)
                vv[j].f4 = *(const float4*)&Vs[(kk4 * 4 + j) * KV_PAD + tx * 4];
            #pragma unroll
            for (int half = 0; half < 2; half++) {
                float4 p4[4];
                #pragma unroll
                for (int i2 = 0; i2 < 4; i2++)
                    p4[i2] = *(const float4*)&Ps[(ty * 8 + half * 4 + i2) * KV_PAD + kk4 * 4];
                #pragma unroll
                for (int i2 = 0; i2 < 4; i2++) {
                    int i = half * 4 + i2;
                    unsigned long long pp0 = dup2(p4[i2].x);
                    FMA2(o01[i], pp0, vv[0].u2[0], o01[i]);
                    FMA2(o23[i], pp0, vv[0].u2[1], o23[i]);
                    unsigned long long pp1 = dup2(p4[i2].y);
                    FMA2(o01[i], pp1, vv[1].u2[0], o01[i]);
                    FMA2(o23[i], pp1, vv[1].u2[1], o23[i]);
                    unsigned long long pp2 = dup2(p4[i2].z);
                    FMA2(o01[i], pp2, vv[2].u2[0], o01[i]);
                    FMA2(o23[i], pp2, vv[2].u2[1], o23[i]);
                    unsigned long long pp3 = dup2(p4[i2].w);
                    FMA2(o01[i], pp3, vv[3].u2[0], o01[i]);
                    FMA2(o23[i], pp3, vv[3].u2[1], o23[i]);
                }
            }
        }
        __syncthreads();
    }

    // Deferred cross-lane reduction: one butterfly over the 16 tx lanes gives
    // every lane the full row totals (same-ty threads are consecutive lanes).
    #pragma unroll
    for (int i = 0; i < 8; i++) {
        float t = lsum[i];
        t += __shfl_xor_sync(0xffffffffu, t, 1);
        t += __shfl_xor_sync(0xffffffffu, t, 2);
        t += __shfl_xor_sync(0xffffffffu, t, 4);
        t += __shfl_xor_sync(0xffffffffu, t, 8);
        lsum[i] = t;
    }

    // Epilogue: divide by (L + 1e-8), write [B,S,H*Dk] (float4)
    #pragma unroll
    for (int i = 0; i < 8; i++) {
        float inv = 1.0f / (lsum[i] + 1e-8f);
        int s_idx = qt * QT + ty * 8 + i;
        float a0, a1, a2, a3;
        upk2(o01[i], a0, a1);
        upk2(o23[i], a2, a3);
        float4 v;
        v.x = a0 * inv;
        v.y = a1 * inv;
        v.z = a2 * inv;
        v.w = a3 * inv;
        *(float4*)&out[((size_t)b * SEQ + s_idx) * D_MODEL + h * D_K + tx * 4] = v;
    }
}

extern "C" void kernel_launch(void* const* d_in, const int* in_sizes, int n_in,
                              void* d_out, int out_size)
{
    const float* x  = (const float*)d_in[0];
    const float* Wq = (const float*)d_in[1];
    const float* bq = (const float*)d_in[2];
    const float* Wk = (const float*)d_in[3];
    const float* bk = (const float*)d_in[4];
    const float* Wv = (const float*)d_in[5];
    const float* bv = (const float*)d_in[6];
    float* out = (float*)d_out;

    float *Qp, *Kp, *Vp;
    cudaGetSymbolAddress((void**)&Qp, g_Q);
    cudaGetSymbolAddress((void**)&Kp, g_K);
    cudaGetSymbolAddress((void**)&Vp, g_V);

    dim3 ggrid(D_MODEL / BN, M_ROWS / BM, 3);   // (8, 32, 3) = 768 CTAs, one launch
    qkv_gemm_fused_kernel<<<ggrid, 256>>>(x, Wq, bq, Wk, bk, Wv, bv, Qp, Kp, Vp);

    size_t smem_bytes = SM_FLOATS * sizeof(float);   // ~103 KB -> 2 CTAs/SM
    cudaFuncSetAttribute(attn_kernel,
                         cudaFuncAttributeMaxDynamicSharedMemorySize,
                         (int)smem_bytes);
    dim3 agrid(SEQ / QT, BATCH * N_HEADS);   // (16, 32)
    attn_kernel<<<agrid, 256, smem_bytes>>>(Qp, Kp, Vp, out);
}